// round 14
// baseline (speedup 1.0000x reference)
#include <cuda_runtime.h>

#define NT   10
#define DIMX 240
#define NSC  64
#define NF   112
#define EPSV 1e-5f
#define RS   4           // replicated accumulator copies (row-subgroups)
#define NBLK 592

// scratch layout: [sum2: NT*DIMX][sum1: NT*NSC][cnt: NT]
#define SCR_SUM1 (NT*DIMX)
#define SCR_CNT  (NT*DIMX + NT*NSC)
#define SCR_SIZE (NT*DIMX + NT*NSC + NT)

__device__ float    g_scr[SCR_SIZE];      // zero at launch; re-zeroed by last apply block
__device__ unsigned g_ready;              // apply arrival counter (reset by last block)

// packed-f32x2 shared-memory RMW: s[0..3] += v*v
__device__ __forceinline__ void rmw_fma2(unsigned sa, unsigned long long v01,
                                         unsigned long long v23) {
    asm volatile(
        "{\n\t"
        ".reg .b64 a0, a1;\n\t"
        "ld.shared.v2.b64 {a0, a1}, [%0];\n\t"
        "fma.rn.f32x2 a0, %1, %1, a0;\n\t"
        "fma.rn.f32x2 a1, %2, %2, a1;\n\t"
        "st.shared.v2.b64 [%0], {a0, a1};\n\t"
        "}"
        :: "r"(sa), "l"(v01), "l"(v23));
}

// packed-f32x2 shared-memory RMW: s[0..3] += v
__device__ __forceinline__ void rmw_add2(unsigned sa, unsigned long long v01,
                                         unsigned long long v23) {
    asm volatile(
        "{\n\t"
        ".reg .b64 a0, a1;\n\t"
        "ld.shared.v2.b64 {a0, a1}, [%0];\n\t"
        "add.rn.f32x2 a0, a0, %1;\n\t"
        "add.rn.f32x2 a1, a1, %2;\n\t"
        "st.shared.v2.b64 [%0], {a0, a1};\n\t"
        "}"
        :: "r"(sa), "l"(v01), "l"(v23));
}

// load one thread-pack: 4 contiguous rows (values + types)
__device__ __forceinline__ void load_pack(const float* __restrict__ x,
                                          const int* __restrict__ ty,
                                          int batch, int r0, int c,
                                          ulonglong2* u, int* t, bool* g) {
#pragma unroll
    for (int i = 0; i < 4; i++) {
        int r = r0 + i;
        g[i] = (r < batch);
        if (g[i]) u[i] = __ldg((const ulonglong2*)(x + (size_t)r * DIMX + c));
    }
    if (r0 + 3 < batch) {
        int4 ta = __ldg((const int4*)(ty + r0));
        t[0] = ta.x; t[1] = ta.y; t[2] = ta.z; t[3] = ta.w;
    } else {
#pragma unroll
        for (int i = 0; i < 4; i++) t[i] = g[i] ? __ldg(ty + r0 + i) : 0;
    }
}

// ---------------------------------------------------------------- stats pass
// Grid-strided, blockDim = 256 (threads 0..239 active in main loop).
//   rs = tid/60 : accumulator copy; owns rows base+4*rs .. base+4*rs+3
//   c4 = tid%60 : float4 column group
// Software-pipelined; ends with the atomic push only (no table build, no tail).
__global__ __launch_bounds__(256, 4) void k_stats(const float* __restrict__ x,
                                                  const int* __restrict__ ty,
                                                  int batch) {
    __shared__ __align__(16) float s2[RS * NT * DIMX];
    __shared__ __align__(16) float s1[RS * NT * NSC];
    __shared__ float scnt[RS * NT];

    const int tid = threadIdx.x;
    for (int i = tid; i < RS * NT * DIMX; i += 256) s2[i] = 0.0f;
    for (int i = tid; i < RS * NT * NSC;  i += 256) s1[i] = 0.0f;
    if (tid < RS * NT) scnt[tid] = 0.0f;
    __syncthreads();

    const int  rs  = tid / 60;
    const int  c4  = tid - rs * 60;
    const int  c   = c4 * 4;
    const bool act = (tid < 240);
    const bool sc  = act && (c4 < 16);   // scalar columns
    const bool cn  = act && (c4 == 0);   // count owner

    const unsigned sa2 = (unsigned)__cvta_generic_to_shared(s2)
                       + (rs * NT * DIMX + c) * 4u;
    const unsigned sa1 = (unsigned)__cvta_generic_to_shared(s1)
                       + (rs * NT * NSC + c) * 4u;

    const int step = gridDim.x * 16;
    int base = blockIdx.x * 16;

    ulonglong2 u[4];  int t[4];  bool g[4];
    if (act && base < batch)
        load_pack(x, ty, batch, base + rs * 4, c, u, t, g);

    for (; base < batch; ) {
        const int nbase = base + step;
        ulonglong2 un[4];  int tn[4];  bool gn[4];
        if (act && nbase < batch)                     // prefetch next pack
            load_pack(x, ty, batch, nbase + rs * 4, c, un, tn, gn);

        if (act) {
#pragma unroll
            for (int i = 0; i < 4; i++) {
                if (g[i]) {
                    rmw_fma2(sa2 + t[i] * (DIMX * 4), u[i].x, u[i].y);
                    if (sc) rmw_add2(sa1 + t[i] * (NSC * 4), u[i].x, u[i].y);
                    if (cn) scnt[rs * NT + t[i]] += 1.0f;
                }
            }
        }
        base = nbase;
#pragma unroll
        for (int i = 0; i < 4; i++) { u[i] = un[i]; t[i] = tn[i]; g[i] = gn[i]; }
    }
    __syncthreads();

    // reduce RS copies, push to global with atomics, exit
    for (int i = tid; i < NT * DIMX; i += 256) {
        float s = s2[i] + s2[NT*DIMX + i] + s2[2*NT*DIMX + i] + s2[3*NT*DIMX + i];
        atomicAdd(&g_scr[i], s);
    }
    for (int i = tid; i < NT * NSC; i += 256) {
        float s = s1[i] + s1[NT*NSC + i] + s1[2*NT*NSC + i] + s1[3*NT*NSC + i];
        atomicAdd(&g_scr[SCR_SUM1 + i], s);
    }
    if (tid < NT) {
        float s = scnt[tid] + scnt[NT + tid] + scnt[2*NT + tid] + scnt[3*NT + tid];
        atomicAdd(&g_scr[SCR_CNT + tid], s);
    }
}

// ---------------------------------------------------------------- apply pass
// Prologue: every block redundantly builds the A/B tables into SMEM from the
// reduced g_scr (12 KB L2-broadcast; overlapped across blocks — no serial tail).
// Main: reversed block order, one contiguous 1024-float4 tile per block,
// 4 float4 per thread, table gathers via LDS, streaming stores.
// Epilogue: the LAST block (arrival counter, incremented after its own
// prologue read) re-zeros g_scr for the next graph replay.
__global__ __launch_bounds__(256) void k_apply(const float4* __restrict__ x4,
                                               const int* __restrict__ ty,
                                               float4* __restrict__ o4,
                                               const float* __restrict__ w,
                                               const float* __restrict__ b,
                                               int n4) {
    __shared__ __align__(16) float sA[NT * DIMX];
    __shared__ __align__(16) float sB[NT * DIMX];
    __shared__ bool sLast;

    const int tid = threadIdx.x;

    // ---- build tables ----
    if (tid < DIMX) {
        const int e = tid;
        for (int tt = 0; tt < NT; tt++) {
            float cnt = fmaxf(g_scr[SCR_CNT + tt], 1.0f);
            float inv = 1.0f / cnt;
            float A, Bv;
            if (e < NSC) {
                float S2   = g_scr[tt * DIMX + e];
                float S1   = g_scr[SCR_SUM1 + tt * NSC + e];
                float mean = S1 * inv;
                float var  = S2 * inv - mean * mean;
                float s    = rsqrtf(var + EPSV) * w[tt * NF + e];
                A  = s;
                Bv = b[tt * NSC + e] - mean * s;
            } else if (e < 64 + 32 * 3) {
                int m    = (e - 64) / 3;
                int bs   = 64 + m * 3;
                float S2 = g_scr[tt * DIMX + bs] + g_scr[tt * DIMX + bs + 1] +
                           g_scr[tt * DIMX + bs + 2];
                float fn = S2 * inv * (1.0f / 3.0f);
                A  = rsqrtf(fn + EPSV) * w[tt * NF + 64 + m];
                Bv = 0.0f;
            } else {
                int m    = (e - 160) / 5;
                int bs   = 160 + m * 5;
                float S2 = 0.0f;
#pragma unroll
                for (int j = 0; j < 5; j++) S2 += g_scr[tt * DIMX + bs + j];
                float fn = S2 * inv * 0.2f;
                A  = rsqrtf(fn + EPSV) * w[tt * NF + 96 + m];
                Bv = 0.0f;
            }
            sA[tt * DIMX + e] = A;
            sB[tt * DIMX + e] = Bv;
        }
    }
    __syncthreads();
    if (tid == 0)    // after this block's g_scr reads are complete
        sLast = (atomicAdd(&g_ready, 1u) == gridDim.x - 1u);

    // ---- main streaming ----
    const unsigned chunk = gridDim.x - 1u - blockIdx.x;
    const unsigned ibase = chunk * 1024u + tid;

    const float4* sA4 = reinterpret_cast<const float4*>(sA);
    const float4* sB4 = reinterpret_cast<const float4*>(sB);

    unsigned idx[4], k[4];
    bool     g[4];
    float4   xv[4];

#pragma unroll
    for (int j = 0; j < 4; j++) {
        idx[j] = ibase + j * 256u;
        g[j]   = idx[j] < (unsigned)n4;
    }
#pragma unroll
    for (int j = 0; j < 4; j++) {
        if (g[j]) {
            unsigned row = idx[j] / 60u;
            unsigned q   = idx[j] - row * 60u;
            int t = __ldg(ty + row);
            k[j]  = t * 60u + q;
            xv[j] = x4[idx[j]];
        }
    }
#pragma unroll
    for (int j = 0; j < 4; j++) {
        if (g[j]) {
            float4 a  = sA4[k[j]];
            float4 bb = sB4[k[j]];
            float4 o;
            o.x = fmaf(xv[j].x, a.x, bb.x);
            o.y = fmaf(xv[j].y, a.y, bb.y);
            o.z = fmaf(xv[j].z, a.z, bb.z);
            o.w = fmaf(xv[j].w, a.w, bb.w);
            __stcs(&o4[idx[j]], o);
        }
    }

    // ---- epilogue: last block resets scratch for next replay ----
    __syncthreads();
    if (sLast) {
        for (int i = tid; i < SCR_SIZE; i += 256) g_scr[i] = 0.0f;
        if (tid == 0) g_ready = 0;
    }
}

// ---------------------------------------------------------------- launch
extern "C" void kernel_launch(void* const* d_in, const int* in_sizes, int n_in,
                              void* d_out, int out_size) {
    const float* x  = (const float*)d_in[0];
    const int*   ty = (const int*)d_in[1];
    const float* w  = (const float*)d_in[2];
    const float* b  = (const float*)d_in[3];

    int batch = in_sizes[0] / DIMX;

    k_stats<<<NBLK, 256>>>(x, ty, batch);

    int n4 = batch * (DIMX / 4);
    k_apply<<<(n4 + 1023) / 1024, 256>>>((const float4*)x, ty, (float4*)d_out,
                                         w, b, n4);
}

// round 16
// speedup vs baseline: 1.7012x; 1.7012x over previous
#include <cuda_runtime.h>

#define NT   10
#define DIMX 240
#define NSC  64
#define NF   112
#define EPSV 1e-5f
#define RS   4           // replicated accumulator copies (row-subgroups)
#define NBLK 592

// scratch layout: [sum2: NT*DIMX][sum1: NT*NSC][cnt: NT]
#define SCR_SUM1 (NT*DIMX)
#define SCR_CNT  (NT*DIMX + NT*NSC)
#define SCR_SIZE (NT*DIMX + NT*NSC + NT)

__device__ float    g_scr[SCR_SIZE];      // static zero-init; re-zeroed by k_apply
__device__ unsigned g_done;               // stats arrival counter (reset by last block)
__device__ __align__(16) float g_A[NT*DIMX];
__device__ __align__(16) float g_B[NT*DIMX];

// packed-f32x2 shared-memory RMW: s[0..3] += v*v
__device__ __forceinline__ void rmw_fma2(unsigned sa, unsigned long long v01,
                                         unsigned long long v23) {
    asm volatile(
        "{\n\t"
        ".reg .b64 a0, a1;\n\t"
        "ld.shared.v2.b64 {a0, a1}, [%0];\n\t"
        "fma.rn.f32x2 a0, %1, %1, a0;\n\t"
        "fma.rn.f32x2 a1, %2, %2, a1;\n\t"
        "st.shared.v2.b64 [%0], {a0, a1};\n\t"
        "}"
        :: "r"(sa), "l"(v01), "l"(v23));
}

// packed-f32x2 shared-memory RMW: s[0..3] += v
__device__ __forceinline__ void rmw_add2(unsigned sa, unsigned long long v01,
                                         unsigned long long v23) {
    asm volatile(
        "{\n\t"
        ".reg .b64 a0, a1;\n\t"
        "ld.shared.v2.b64 {a0, a1}, [%0];\n\t"
        "add.rn.f32x2 a0, a0, %1;\n\t"
        "add.rn.f32x2 a1, a1, %2;\n\t"
        "st.shared.v2.b64 [%0], {a0, a1};\n\t"
        "}"
        :: "r"(sa), "l"(v01), "l"(v23));
}

// load one thread-pack: 4 contiguous rows (values + types)
__device__ __forceinline__ void load_pack(const float* __restrict__ x,
                                          const int* __restrict__ ty,
                                          int batch, int r0, int c,
                                          ulonglong2* u, int* t, bool* g) {
#pragma unroll
    for (int i = 0; i < 4; i++) {
        int r = r0 + i;
        g[i] = (r < batch);
        if (g[i]) u[i] = __ldg((const ulonglong2*)(x + (size_t)r * DIMX + c));
    }
    if (r0 + 3 < batch) {
        int4 ta = __ldg((const int4*)(ty + r0));
        t[0] = ta.x; t[1] = ta.y; t[2] = ta.z; t[3] = ta.w;
    } else {
#pragma unroll
        for (int i = 0; i < 4; i++) t[i] = g[i] ? __ldg(ty + r0 + i) : 0;
    }
}

// ---------------------------------------------------------------- stats pass
// Grid-strided, blockDim = 256 (threads 0..239 active in main loop).
//   rs = tid/60 : accumulator copy; owns rows base+4*rs .. base+4*rs+3
//   c4 = tid%60 : float4 column group
// Software-pipelined; last block to finish builds the A/B tables (fused).
__global__ __launch_bounds__(256) void k_stats(const float* __restrict__ x,
                                               const int* __restrict__ ty,
                                               const float* __restrict__ w,
                                               const float* __restrict__ b,
                                               int batch) {
    __shared__ __align__(16) float s2[RS * NT * DIMX];
    __shared__ __align__(16) float s1[RS * NT * NSC];
    __shared__ float scnt[RS * NT];
    __shared__ unsigned sIsLast;

    const int tid = threadIdx.x;
    for (int i = tid; i < RS * NT * DIMX; i += 256) s2[i] = 0.0f;
    for (int i = tid; i < RS * NT * NSC;  i += 256) s1[i] = 0.0f;
    if (tid < RS * NT) scnt[tid] = 0.0f;
    __syncthreads();

    const int  rs  = tid / 60;
    const int  c4  = tid - rs * 60;
    const int  c   = c4 * 4;
    const bool act = (tid < 240);
    const bool sc  = act && (c4 < 16);   // scalar columns
    const bool cn  = act && (c4 == 0);   // count owner

    const unsigned sa2 = (unsigned)__cvta_generic_to_shared(s2)
                       + (rs * NT * DIMX + c) * 4u;
    const unsigned sa1 = (unsigned)__cvta_generic_to_shared(s1)
                       + (rs * NT * NSC + c) * 4u;

    const int step = gridDim.x * 16;
    int base = blockIdx.x * 16;

    ulonglong2 u[4];  int t[4];  bool g[4];
    if (act && base < batch)
        load_pack(x, ty, batch, base + rs * 4, c, u, t, g);

    for (; base < batch; ) {
        const int nbase = base + step;
        ulonglong2 un[4];  int tn[4];  bool gn[4];
        if (act && nbase < batch)                     // prefetch next pack
            load_pack(x, ty, batch, nbase + rs * 4, c, un, tn, gn);

        if (act) {
#pragma unroll
            for (int i = 0; i < 4; i++) {
                if (g[i]) {
                    rmw_fma2(sa2 + t[i] * (DIMX * 4), u[i].x, u[i].y);
                    if (sc) rmw_add2(sa1 + t[i] * (NSC * 4), u[i].x, u[i].y);
                    if (cn) scnt[rs * NT + t[i]] += 1.0f;
                }
            }
        }
        base = nbase;
#pragma unroll
        for (int i = 0; i < 4; i++) { u[i] = un[i]; t[i] = tn[i]; g[i] = gn[i]; }
    }
    __syncthreads();

    // reduce RS copies, push to global with atomics
    for (int i = tid; i < NT * DIMX; i += 256) {
        float s = s2[i] + s2[NT*DIMX + i] + s2[2*NT*DIMX + i] + s2[3*NT*DIMX + i];
        atomicAdd(&g_scr[i], s);
    }
    for (int i = tid; i < NT * NSC; i += 256) {
        float s = s1[i] + s1[NT*NSC + i] + s1[2*NT*NSC + i] + s1[3*NT*NSC + i];
        atomicAdd(&g_scr[SCR_SUM1 + i], s);
    }
    if (tid < NT) {
        float s = scnt[tid] + scnt[NT + tid] + scnt[2*NT + tid] + scnt[3*NT + tid];
        atomicAdd(&g_scr[SCR_CNT + tid], s);
    }

    // ---- fused table build: last block to arrive does it ----
    __threadfence();
    __syncthreads();
    if (tid == 0)
        sIsLast = (atomicAdd(&g_done, 1u) == gridDim.x - 1u);
    __syncthreads();
    if (!sIsLast) return;
    __threadfence();                      // acquire all blocks' atomics

    const int e = tid;
    if (e < DIMX) {
        for (int tt = 0; tt < NT; tt++) {
            float cnt = fmaxf(g_scr[SCR_CNT + tt], 1.0f);
            float inv = 1.0f / cnt;
            float A, Bv;
            if (e < NSC) {
                float S2   = g_scr[tt * DIMX + e];
                float S1   = g_scr[SCR_SUM1 + tt * NSC + e];
                float mean = S1 * inv;
                float var  = S2 * inv - mean * mean;
                float s    = rsqrtf(var + EPSV) * w[tt * NF + e];
                A  = s;
                Bv = b[tt * NSC + e] - mean * s;
            } else if (e < 64 + 32 * 3) {
                int m    = (e - 64) / 3;
                int bs   = 64 + m * 3;
                float S2 = g_scr[tt * DIMX + bs] + g_scr[tt * DIMX + bs + 1] +
                           g_scr[tt * DIMX + bs + 2];
                float fn = S2 * inv * (1.0f / 3.0f);
                A  = rsqrtf(fn + EPSV) * w[tt * NF + 64 + m];
                Bv = 0.0f;
            } else {
                int m    = (e - 160) / 5;
                int bs   = 160 + m * 5;
                float S2 = 0.0f;
#pragma unroll
                for (int j = 0; j < 5; j++) S2 += g_scr[tt * DIMX + bs + j];
                float fn = S2 * inv * 0.2f;
                A  = rsqrtf(fn + EPSV) * w[tt * NF + 96 + m];
                Bv = 0.0f;
            }
            g_A[tt * DIMX + e] = A;
            g_B[tt * DIMX + e] = Bv;
        }
    }
    if (tid == 0) g_done = 0;             // reset for next graph replay
}

// ---------------------------------------------------------------- apply pass
// Reversed block order, one contiguous 1024-float4 (16 KB) tile per block,
// 4 float4 per thread. DRAM-critical loads (x, ty) front-batched; table
// loads (L1-hot, 19.2 KB working set) issued per-j in the tail so they
// don't occupy long-lived registers. 48-reg budget -> 5 CTAs/SM.
// Block 0 re-zeros the stats scratch for the next graph replay.
__global__ __launch_bounds__(256, 5) void k_apply(const float4* __restrict__ x4,
                                                  const int* __restrict__ ty,
                                                  float4* __restrict__ o4,
                                                  int n4) {
    if (blockIdx.x == 0) {                 // g_scr is dead now (tables built)
        for (int i = threadIdx.x; i < SCR_SIZE; i += 256) g_scr[i] = 0.0f;
    }

    const unsigned chunk = gridDim.x - 1u - blockIdx.x;
    const unsigned ibase = chunk * 1024u + threadIdx.x;

    const float4* A4 = reinterpret_cast<const float4*>(g_A);
    const float4* B4 = reinterpret_cast<const float4*>(g_B);

    unsigned idx[4], k[4];
    bool     g[4];
    float4   xv[4];

#pragma unroll
    for (int j = 0; j < 4; j++) {
        idx[j] = ibase + j * 256u;
        g[j]   = idx[j] < (unsigned)n4;
    }
#pragma unroll
    for (int j = 0; j < 4; j++) {
        if (g[j]) {
            unsigned row = idx[j] / 60u;
            unsigned q   = idx[j] - row * 60u;
            int t = __ldg(ty + row);
            k[j]  = t * 60u + q;
            xv[j] = x4[idx[j]];
        }
    }
#pragma unroll
    for (int j = 0; j < 4; j++) {
        if (g[j]) {
            float4 a  = A4[k[j]];          // L1-hit gathers, loaded just-in-time
            float4 bb = B4[k[j]];
            float4 o;
            o.x = fmaf(xv[j].x, a.x, bb.x);
            o.y = fmaf(xv[j].y, a.y, bb.y);
            o.z = fmaf(xv[j].z, a.z, bb.z);
            o.w = fmaf(xv[j].w, a.w, bb.w);
            __stcs(&o4[idx[j]], o);
        }
    }
}

// ---------------------------------------------------------------- launch
extern "C" void kernel_launch(void* const* d_in, const int* in_sizes, int n_in,
                              void* d_out, int out_size) {
    const float* x  = (const float*)d_in[0];
    const int*   ty = (const int*)d_in[1];
    const float* w  = (const float*)d_in[2];
    const float* b  = (const float*)d_in[3];

    int batch = in_sizes[0] / DIMX;

    k_stats<<<NBLK, 256>>>(x, ty, w, b, batch);

    int n4 = batch * (DIMX / 4);
    k_apply<<<(n4 + 1023) / 1024, 256>>>((const float4*)x, ty, (float4*)d_out, n4);
}